// round 3
// baseline (speedup 1.0000x reference)
#include <cuda_runtime.h>
#include <cstdint>

// Problem constants
#define BB 8
#define LL 4096
#define DD 768
#define NCHUNK 256                      // L split into 256 chunks of 16 rows
#define ROWS_PER_CHUNK (LL / NCHUNK)    // 16

// Scratch (device globals; no allocation allowed)
__device__ __align__(16) float g_part[BB * NCHUNK * DD];  // partial column sums (6 MB)
__device__ __align__(16) float g_sum[BB * DD];            // full column sums
__device__ float g_coef[BB];                              // ||sum||^2 / (D^2 L^4)

// ---------------------------------------------------------------------------
// Kernel 1: partial column sums. grid (NCHUNK, BB) = 2048 blocks, 192 threads.
// Each thread owns one float4 column group (192*4 = 768) and sums 16 rows.
// High block count -> high occupancy -> many outstanding LDG.128 to push HBM.
// x stays cached in L2 (default policy) for reuse by kernel 3.
// ---------------------------------------------------------------------------
__global__ __launch_bounds__(192) void colsum_partial_kernel(const float* __restrict__ x) {
    const int c = blockIdx.x;   // chunk
    const int b = blockIdx.y;   // batch
    const int t = threadIdx.x;  // 0..191, float4 lane within row

    const float4* xp = reinterpret_cast<const float4*>(
        x + ((size_t)b * LL + (size_t)c * ROWS_PER_CHUNK) * DD) + t;

    float4 s0 = make_float4(0.f, 0.f, 0.f, 0.f);
    float4 s1 = make_float4(0.f, 0.f, 0.f, 0.f);
#pragma unroll
    for (int i = 0; i < ROWS_PER_CHUNK; i += 2) {
        float4 v0 = xp[(size_t)i * (DD / 4)];
        float4 v1 = xp[(size_t)(i + 1) * (DD / 4)];
        s0.x += v0.x; s0.y += v0.y; s0.z += v0.z; s0.w += v0.w;
        s1.x += v1.x; s1.y += v1.y; s1.z += v1.z; s1.w += v1.w;
    }
    float4 s = make_float4(s0.x + s1.x, s0.y + s1.y, s0.z + s1.z, s0.w + s1.w);
    reinterpret_cast<float4*>(g_part)[((size_t)b * NCHUNK + c) * (DD / 4) + t] = s;
}

// ---------------------------------------------------------------------------
// Kernel 2: finish the reduction + compute coef[b]. grid BB, block 256.
// Deterministic (fixed summation order), tiny traffic (6 MB, L2-resident).
// ---------------------------------------------------------------------------
__global__ __launch_bounds__(256) void reduce_coef_kernel() {
    const int b = blockIdx.x;
    float sq = 0.f;
    for (int d = threadIdx.x; d < DD; d += 256) {
        float s = 0.f;
#pragma unroll 8
        for (int c = 0; c < NCHUNK; c++)
            s += g_part[((size_t)b * NCHUNK + c) * DD + d];
        g_sum[b * DD + d] = s;
        sq += s * s;
    }
    __shared__ float red[256];
    red[threadIdx.x] = sq;
    __syncthreads();
    for (int o = 128; o > 0; o >>= 1) {
        if (threadIdx.x < o) red[threadIdx.x] += red[threadIdx.x + o];
        __syncthreads();
    }
    if (threadIdx.x == 0) {
        // coef = ||sum||^2 / (D^2 * L^4)
        double denom = (double)DD * (double)DD
                     * (double)LL * (double)LL * (double)LL * (double)LL;
        g_coef[b] = (float)((double)red[0] / denom);
    }
}

// ---------------------------------------------------------------------------
// Kernel 3: out[b,l,:] = alpha[l] + (x[b,l]·sum_b)*coef[b] * x[b,l,:]
// One warp per row; row held in registers (6 float4/lane) and reused for the
// dot product and the scaled write. x reads use __ldcs: each x line is dead
// after this single read, so evict-first keeps L2 capacity free for the
// output write allocations instead of thrashing still-unread x lines.
// Stores are plain STG (R2 showed .cs stores regress the write path).
// ---------------------------------------------------------------------------
__global__ __launch_bounds__(256) void finalize_kernel(const float* __restrict__ x,
                                                       const float* __restrict__ alpha,
                                                       float* __restrict__ out) {
    __shared__ float4 smean[DD / 4];   // 192 float4 = sum_b row

    const int rowbase = blockIdx.x * 8;
    const int b = rowbase >> 12;       // 4096 rows per batch, 8 | 4096 -> same b

    if (threadIdx.x < DD / 4)
        smean[threadIdx.x] = reinterpret_cast<const float4*>(g_sum + b * DD)[threadIdx.x];
    __syncthreads();

    const int warp = threadIdx.x >> 5;
    const int lane = threadIdx.x & 31;
    const int row  = rowbase + warp;
    const int l    = row & (LL - 1);

    const float4* xp = reinterpret_cast<const float4*>(x + (size_t)row * DD);
    float4 v[6];
    float dot = 0.f;
#pragma unroll
    for (int i = 0; i < 6; i++) {
        v[i] = __ldcs(xp + lane + i * 32);   // last use of this x line
        float4 m = smean[lane + i * 32];
        dot += v[i].x * m.x + v[i].y * m.y + v[i].z * m.z + v[i].w * m.w;
    }
#pragma unroll
    for (int off = 16; off > 0; off >>= 1)
        dot += __shfl_xor_sync(0xFFFFFFFFu, dot, off);

    const float y2 = dot * g_coef[b];
    const float a  = alpha[l];

    float4* op = reinterpret_cast<float4*>(out + (size_t)row * DD);
#pragma unroll
    for (int i = 0; i < 6; i++) {
        float4 o;
        o.x = a + y2 * v[i].x;
        o.y = a + y2 * v[i].y;
        o.z = a + y2 * v[i].z;
        o.w = a + y2 * v[i].w;
        op[lane + i * 32] = o;
    }
}

extern "C" void kernel_launch(void* const* d_in, const int* in_sizes, int n_in,
                              void* d_out, int out_size) {
    const float* x     = (const float*)d_in[0];   // [8, 4096, 768] f32
    const float* alpha = (const float*)d_in[1];   // [4096, 1] f32
    float* out = (float*)d_out;                   // [8, 4096, 768] f32

    colsum_partial_kernel<<<dim3(NCHUNK, BB), 192>>>(x);
    reduce_coef_kernel<<<BB, 256>>>();
    finalize_kernel<<<(BB * LL) / 8, 256>>>(x, alpha, out);
}

// round 4
// speedup vs baseline: 1.1003x; 1.1003x over previous
#include <cuda_runtime.h>
#include <cstdint>

// Problem constants
#define BB 8
#define LL 4096
#define DD 768
#define BPS 4                          // batches per slice (x_slice = 50MB, fits L2 with out_slice)
#define NSLICE (BB / BPS)              // 2
#define NCHUNK 256                     // L chunks per batch in k1
#define RPC (LL / NCHUNK)              // 16 rows per chunk
#define DG 8                           // D groups in k2
#define DPG (DD / DG)                  // 96 columns per group

// Scratch (device globals; no allocation allowed). NO .cs hints anywhere (R2/R3 regressions).
__device__ __align__(16) float g_part[BB * NCHUNK * DD];   // partial column sums (6 MB)
__device__ __align__(16) float g_sum[BB * DD];             // full column sums
__device__ float g_sqpart[BB * DG];                        // per-dgroup sum of squares

// ---------------------------------------------------------------------------
// Kernel 1 (per slice): partial column sums over one 4-batch slice.
// grid (NCHUNK, BPS) = 1024 blocks, 192 threads; thread owns one float4 column
// group and sums 16 rows. Leaves x_slice resident in L2 for kernel 3.
// ---------------------------------------------------------------------------
__global__ __launch_bounds__(192) void colsum_partial_kernel(const float* __restrict__ x,
                                                             int base_b) {
    const int c = blockIdx.x;             // chunk
    const int b = base_b + blockIdx.y;    // global batch
    const int t = threadIdx.x;            // 0..191

    const float4* xp = reinterpret_cast<const float4*>(
        x + ((size_t)b * LL + (size_t)c * RPC) * DD) + t;

    float4 s0 = make_float4(0.f, 0.f, 0.f, 0.f);
    float4 s1 = make_float4(0.f, 0.f, 0.f, 0.f);
#pragma unroll
    for (int i = 0; i < RPC; i += 2) {
        float4 v0 = xp[(size_t)i * (DD / 4)];
        float4 v1 = xp[(size_t)(i + 1) * (DD / 4)];
        s0.x += v0.x; s0.y += v0.y; s0.z += v0.z; s0.w += v0.w;
        s1.x += v1.x; s1.y += v1.y; s1.z += v1.z; s1.w += v1.w;
    }
    float4 s = make_float4(s0.x + s1.x, s0.y + s1.y, s0.z + s1.z, s0.w + s1.w);
    reinterpret_cast<float4*>(g_part)[((size_t)b * NCHUNK + c) * (DD / 4) + t] = s;
}

// ---------------------------------------------------------------------------
// Kernel 2 (per slice): finish column sums + per-dgroup sum of squares.
// grid (BPS, DG) = 32 blocks x 96 threads: block (b,g) reduces 256 chunk
// partials for its 96 columns (coalesced: 32 consecutive d = one 128B line),
// writes g_sum and one fixed-order block-reduced square-sum. Deterministic.
// ---------------------------------------------------------------------------
__global__ __launch_bounds__(96) void reduce_kernel(int base_b) {
    const int b = base_b + blockIdx.x;
    const int g = blockIdx.y;
    const int d = g * DPG + threadIdx.x;

    float s = 0.f;
    const float* p = g_part + (size_t)b * NCHUNK * DD + d;
#pragma unroll 8
    for (int c = 0; c < NCHUNK; c++)
        s += p[(size_t)c * DD];
    g_sum[b * DD + d] = s;

    __shared__ float red[96];
    red[threadIdx.x] = s * s;
    __syncthreads();
    // fixed-order tree over 96 = 3 * 32
    if (threadIdx.x < 32) {
        float v = red[threadIdx.x] + red[threadIdx.x + 32] + red[threadIdx.x + 64];
#pragma unroll
        for (int off = 16; off > 0; off >>= 1)
            v += __shfl_xor_sync(0xFFFFFFFFu, v, off);
        if (threadIdx.x == 0) g_sqpart[b * DG + g] = v;
    }
}

// ---------------------------------------------------------------------------
// Kernel 3 (per slice): out[b,l,:] = alpha[l] + (x[b,l]·sum_b)*coef[b]*x[b,l,:]
// One warp per row; row cached in registers for dot + scaled write.
// x_slice reads are L2 hits (50MB x + <=50MB out < 126MB L2) -> write-bound.
// coef[b] computed inline from the 8 dgroup partials (fixed order).
// ---------------------------------------------------------------------------
__global__ __launch_bounds__(256) void finalize_kernel(const float* __restrict__ x,
                                                       const float* __restrict__ alpha,
                                                       float* __restrict__ out,
                                                       int base_row) {
    __shared__ float4 smean[DD / 4];   // sum_b row
    __shared__ float scoef;

    const int rowbase = base_row + blockIdx.x * 8;
    const int b = rowbase >> 12;       // 8 | 4096 -> whole block same batch

    if (threadIdx.x < DD / 4)
        smean[threadIdx.x] = reinterpret_cast<const float4*>(g_sum + b * DD)[threadIdx.x];
    if (threadIdx.x == 0) {
        float sq = 0.f;
#pragma unroll
        for (int g = 0; g < DG; g++) sq += g_sqpart[b * DG + g];
        const double denom = (double)DD * (double)DD
                           * (double)LL * (double)LL * (double)LL * (double)LL;
        scoef = (float)((double)sq / denom);
    }
    __syncthreads();

    const int warp = threadIdx.x >> 5;
    const int lane = threadIdx.x & 31;
    const int row  = rowbase + warp;
    const int l    = row & (LL - 1);

    const float4* xp = reinterpret_cast<const float4*>(x + (size_t)row * DD);
    float4 v[6];
    float dot = 0.f;
#pragma unroll
    for (int i = 0; i < 6; i++) {
        v[i] = xp[lane + i * 32];
        float4 m = smean[lane + i * 32];
        dot += v[i].x * m.x + v[i].y * m.y + v[i].z * m.z + v[i].w * m.w;
    }
#pragma unroll
    for (int off = 16; off > 0; off >>= 1)
        dot += __shfl_xor_sync(0xFFFFFFFFu, dot, off);

    const float y2 = dot * scoef;
    const float a  = alpha[l];

    float4* op = reinterpret_cast<float4*>(out + (size_t)row * DD);
#pragma unroll
    for (int i = 0; i < 6; i++) {
        float4 o;
        o.x = a + y2 * v[i].x;
        o.y = a + y2 * v[i].y;
        o.z = a + y2 * v[i].z;
        o.w = a + y2 * v[i].w;
        op[lane + i * 32] = o;
    }
}

extern "C" void kernel_launch(void* const* d_in, const int* in_sizes, int n_in,
                              void* d_out, int out_size) {
    const float* x     = (const float*)d_in[0];   // [8, 4096, 768] f32
    const float* alpha = (const float*)d_in[1];   // [4096, 1] f32
    float* out = (float*)d_out;                   // [8, 4096, 768] f32

    for (int s = 0; s < NSLICE; s++) {
        const int base_b = s * BPS;
        colsum_partial_kernel<<<dim3(NCHUNK, BPS), 192>>>(x, base_b);
        reduce_kernel<<<dim3(BPS, DG), 96>>>(base_b);
        finalize_kernel<<<(BPS * LL) / 8, 256>>>(x, alpha, out, base_b * LL);
    }
}

// round 5
// speedup vs baseline: 1.5034x; 1.3664x over previous
#include <cuda_runtime.h>
#include <cstdint>

// Problem constants
#define BB 8
#define LL 4096
#define DD 768
#define NCHUNK 128                     // L chunks per batch in k1 (best measured)
#define RPC (LL / NCHUNK)              // 32 rows per chunk
#define DG 8                           // D groups in k2
#define DPG (DD / DG)                  // 96 columns per group

// Scratch (device globals; no allocation allowed). No .cs/.cv hints anywhere
// (R2/R3 showed they regress hard on this workload).
__device__ __align__(16) float g_part[BB * NCHUNK * DD];   // partial column sums (3 MB)
__device__ __align__(16) float g_sum[BB * DD];             // full column sums
__device__ float g_sqpart[BB * DG];                        // per-dgroup sum of squares

// ---------------------------------------------------------------------------
// Kernel 1: partial column sums. grid (NCHUNK, BB) = 1024 blocks, 192 threads.
// Each thread owns one float4 column group (192*4 = 768) and sums 32 rows with
// 4 independent accumulators (front-batched loads -> higher MLP).
// ---------------------------------------------------------------------------
__global__ __launch_bounds__(192) void colsum_partial_kernel(const float* __restrict__ x) {
    const int c = blockIdx.x;   // chunk
    const int b = blockIdx.y;   // batch
    const int t = threadIdx.x;  // 0..191

    const float4* xp = reinterpret_cast<const float4*>(
        x + ((size_t)b * LL + (size_t)c * RPC) * DD) + t;

    float4 s0 = make_float4(0.f, 0.f, 0.f, 0.f);
    float4 s1 = make_float4(0.f, 0.f, 0.f, 0.f);
    float4 s2 = make_float4(0.f, 0.f, 0.f, 0.f);
    float4 s3 = make_float4(0.f, 0.f, 0.f, 0.f);
#pragma unroll
    for (int i = 0; i < RPC; i += 4) {
        float4 v0 = xp[(size_t)(i + 0) * (DD / 4)];
        float4 v1 = xp[(size_t)(i + 1) * (DD / 4)];
        float4 v2 = xp[(size_t)(i + 2) * (DD / 4)];
        float4 v3 = xp[(size_t)(i + 3) * (DD / 4)];
        s0.x += v0.x; s0.y += v0.y; s0.z += v0.z; s0.w += v0.w;
        s1.x += v1.x; s1.y += v1.y; s1.z += v1.z; s1.w += v1.w;
        s2.x += v2.x; s2.y += v2.y; s2.z += v2.z; s2.w += v2.w;
        s3.x += v3.x; s3.y += v3.y; s3.z += v3.z; s3.w += v3.w;
    }
    float4 s = make_float4((s0.x + s1.x) + (s2.x + s3.x),
                           (s0.y + s1.y) + (s2.y + s3.y),
                           (s0.z + s1.z) + (s2.z + s3.z),
                           (s0.w + s1.w) + (s2.w + s3.w));
    reinterpret_cast<float4*>(g_part)[((size_t)b * NCHUNK + c) * (DD / 4) + t] = s;
}

// ---------------------------------------------------------------------------
// Kernel 2: finish column sums + per-dgroup sum of squares.
// grid (BB, DG) = 64 blocks x 96 threads: block (b,g) reduces 128 chunk
// partials for its 96 columns, writes g_sum and one fixed-order block-reduced
// square-sum. Deterministic; ~1.5 MB traffic, mostly L2-resident.
// ---------------------------------------------------------------------------
__global__ __launch_bounds__(96) void reduce_kernel() {
    const int b = blockIdx.x;
    const int g = blockIdx.y;
    const int d = g * DPG + threadIdx.x;

    float s = 0.f;
    const float* p = g_part + (size_t)b * NCHUNK * DD + d;
#pragma unroll 8
    for (int c = 0; c < NCHUNK; c++)
        s += p[(size_t)c * DD];
    g_sum[b * DD + d] = s;

    __shared__ float red[96];
    red[threadIdx.x] = s * s;
    __syncthreads();
    if (threadIdx.x < 32) {
        float v = red[threadIdx.x] + red[threadIdx.x + 32] + red[threadIdx.x + 64];
#pragma unroll
        for (int off = 16; off > 0; off >>= 1)
            v += __shfl_xor_sync(0xFFFFFFFFu, v, off);
        if (threadIdx.x == 0) g_sqpart[b * DG + g] = v;
    }
}

// ---------------------------------------------------------------------------
// Kernel 3: out[b,l,:] = alpha[l] + (x[b,l]·sum_b)*coef[b]*x[b,l,:]
// One warp per row; row cached in registers (6 float4/lane), reused for dot
// and scaled write. coef computed inline from the 8 dgroup partials (fixed
// order -> deterministic). Plain LDG/STG only.
// ---------------------------------------------------------------------------
__global__ __launch_bounds__(256) void finalize_kernel(const float* __restrict__ x,
                                                       const float* __restrict__ alpha,
                                                       float* __restrict__ out) {
    __shared__ float4 smean[DD / 4];   // sum_b row
    __shared__ float scoef;

    const int rowbase = blockIdx.x * 8;
    const int b = rowbase >> 12;       // 8 | 4096 -> whole block same batch

    if (threadIdx.x < DD / 4)
        smean[threadIdx.x] = reinterpret_cast<const float4*>(g_sum + b * DD)[threadIdx.x];
    if (threadIdx.x == 0) {
        float sq = 0.f;
#pragma unroll
        for (int g = 0; g < DG; g++) sq += g_sqpart[b * DG + g];
        const double denom = (double)DD * (double)DD
                           * (double)LL * (double)LL * (double)LL * (double)LL;
        scoef = (float)((double)sq / denom);
    }
    __syncthreads();

    const int warp = threadIdx.x >> 5;
    const int lane = threadIdx.x & 31;
    const int row  = rowbase + warp;
    const int l    = row & (LL - 1);

    const float4* xp = reinterpret_cast<const float4*>(x + (size_t)row * DD);
    float4 v[6];
    float dot = 0.f;
#pragma unroll
    for (int i = 0; i < 6; i++) {
        v[i] = xp[lane + i * 32];
        float4 m = smean[lane + i * 32];
        dot += v[i].x * m.x + v[i].y * m.y + v[i].z * m.z + v[i].w * m.w;
    }
#pragma unroll
    for (int off = 16; off > 0; off >>= 1)
        dot += __shfl_xor_sync(0xFFFFFFFFu, dot, off);

    const float y2 = dot * scoef;
    const float a  = alpha[l];

    float4* op = reinterpret_cast<float4*>(out + (size_t)row * DD);
#pragma unroll
    for (int i = 0; i < 6; i++) {
        float4 o;
        o.x = a + y2 * v[i].x;
        o.y = a + y2 * v[i].y;
        o.z = a + y2 * v[i].z;
        o.w = a + y2 * v[i].w;
        op[lane + i * 32] = o;
    }
}

extern "C" void kernel_launch(void* const* d_in, const int* in_sizes, int n_in,
                              void* d_out, int out_size) {
    const float* x     = (const float*)d_in[0];   // [8, 4096, 768] f32
    const float* alpha = (const float*)d_in[1];   // [4096, 1] f32
    float* out = (float*)d_out;                   // [8, 4096, 768] f32

    colsum_partial_kernel<<<dim3(NCHUNK, BB), 192>>>(x);
    reduce_kernel<<<dim3(BB, DG), 96>>>();
    finalize_kernel<<<(BB * LL) / 8, 256>>>(x, alpha, out);
}